// round 2
// baseline (speedup 1.0000x reference)
#include <cuda_runtime.h>
#include <cuda_bf16.h>

// Problem constants
#define D_DIM   1024
#define L_COMP  16384
#define L_FULL  32768
#define EPS_P   1e-4f

#define CHUNK_T 128                  // positions per chunk
#define NCHUNK  (L_COMP / CHUNK_T)   // 128 chunks

// Scratch (allocation-free rule: __device__ globals)
__device__ float g_p[L_COMP];              // clipped p
__device__ float g_A[NCHUNK];              // per-chunk decay product (scalar)
__device__ float g_Z[NCHUNK * D_DIM];      // chunk-local scan endpoints
__device__ float g_carry[NCHUNK * D_DIM];  // carry entering each chunk
__device__ int   g_pos[L_COMP + 1];        // boundary positions; g_pos[L_COMP] = L_FULL

// ---------------------------------------------------------------------------
// prep: blocks 0..15 clip p; block 16 computes chunk products; block 17 scans b
// ---------------------------------------------------------------------------
__global__ void k_prep(const float* __restrict__ ps, const int* __restrict__ b) {
    int blk = blockIdx.x;
    int tid = threadIdx.x;
    if (blk < 16) {
        int i = blk * 1024 + tid;
        float p = ps[i];
        p = fminf(fmaxf(p, EPS_P), 1.0f - EPS_P);
        g_p[i] = p;
    } else if (blk == 16) {
        if (tid < NCHUNK) {
            int t0 = tid * CHUNK_T;
            float prod = 1.0f;
            #pragma unroll 8
            for (int t = 0; t < CHUNK_T; t++) {
                float p = ps[t0 + t];
                p = fminf(fmaxf(p, EPS_P), 1.0f - EPS_P);
                prod *= (1.0f - p);
            }
            g_A[tid] = prod;
        }
    } else {
        // boundary position scan: 1024 threads x 32 elements = 32768
        __shared__ int s[1024];
        int base = tid * 32;
        int cnt = 0;
        #pragma unroll 8
        for (int i = 0; i < 32; i++) cnt += b[base + i];
        s[tid] = cnt;
        __syncthreads();
        // Hillis-Steele inclusive scan over 1024 entries
        for (int off = 1; off < 1024; off <<= 1) {
            int v = s[tid];
            int u = (tid >= off) ? s[tid - off] : 0;
            __syncthreads();
            s[tid] = v + u;
            __syncthreads();
        }
        int run = s[tid] - cnt;  // exclusive prefix
        #pragma unroll 8
        for (int i = 0; i < 32; i++) {
            if (b[base + i]) g_pos[run++] = base + i;
        }
        if (tid == 1023) g_pos[s[1023]] = L_FULL;  // total ones == L_COMP
    }
}

// ---------------------------------------------------------------------------
// pass1: chunk-local scans from zero state -> Z endpoints
// grid: (D/256, NCHUNK), block: 256
// ---------------------------------------------------------------------------
__global__ void k_pass1(const float* __restrict__ x) {
    int c = blockIdx.y;
    int d = blockIdx.x * blockDim.x + threadIdx.x;
    int t0 = c * CHUNK_T;
    const float* xp = x + (size_t)t0 * D_DIM + d;
    float z = 0.0f;
    #pragma unroll 4
    for (int t = 0; t < CHUNK_T; t++) {
        float p = g_p[t0 + t];                       // warp-uniform, cached
        float xv = xp[(size_t)t * D_DIM];            // coalesced 128B/warp
        z = fmaf(1.0f - p, z, p * xv);
    }
    g_Z[c * D_DIM + d] = z;
}

// ---------------------------------------------------------------------------
// pass2: cross-chunk recurrence, one block of 1024 threads (one per channel)
// carry_in[c] = scan of (A, Z) over chunks 0..c-1
// ---------------------------------------------------------------------------
__global__ void k_pass2() {
    int d = threadIdx.x;
    float carry = 0.0f;
    for (int c0 = 0; c0 < NCHUNK; c0 += 8) {
        float zb[8], ab[8];
        #pragma unroll
        for (int j = 0; j < 8; j++) {
            zb[j] = g_Z[(c0 + j) * D_DIM + d];
            ab[j] = g_A[c0 + j];
        }
        #pragma unroll
        for (int j = 0; j < 8; j++) {
            g_carry[(c0 + j) * D_DIM + d] = carry;
            carry = fmaf(ab[j], carry, zb[j]);
        }
    }
}

// ---------------------------------------------------------------------------
// pass3: re-scan with carry, fused scatter-replicate into out
// grid: (D/256, NCHUNK), block: 256
// ---------------------------------------------------------------------------
__global__ void k_pass3(const float* __restrict__ x, float* __restrict__ out) {
    int c = blockIdx.y;
    int d = blockIdx.x * blockDim.x + threadIdx.x;
    int t0 = c * CHUNK_T;
    const float* xp = x + (size_t)t0 * D_DIM + d;
    float z = g_carry[c * D_DIM + d];
    int seg_s = g_pos[t0];
    #pragma unroll 2
    for (int t = 0; t < CHUNK_T; t++) {
        float p = g_p[t0 + t];
        float xv = xp[(size_t)t * D_DIM];
        z = fmaf(1.0f - p, z, p * xv);
        int seg_e = g_pos[t0 + t + 1];               // warp-uniform
        for (int tf = seg_s; tf < seg_e; tf++) {     // warp-uniform trip count
            out[(size_t)tf * D_DIM + d] = z;         // coalesced writes
        }
        seg_s = seg_e;
    }
}

// ---------------------------------------------------------------------------
extern "C" void kernel_launch(void* const* d_in, const int* in_sizes, int n_in,
                              void* d_out, int out_size) {
    const float* x  = (const float*)d_in[0];   // (1, 16384, 1024) f32
    const float* ps = (const float*)d_in[1];   // (16384,) f32
    const int*   b  = (const int*)d_in[2];     // (1, 32768) i32
    float* out = (float*)d_out;                // (1, 32768, 1024) f32

    k_prep<<<18, 1024>>>(ps, b);
    dim3 grid(D_DIM / 256, NCHUNK);
    k_pass1<<<grid, 256>>>(x);
    k_pass2<<<1, 1024>>>();
    k_pass3<<<grid, 256>>>(x, out);
}

// round 7
// speedup vs baseline: 1.2550x; 1.2550x over previous
#include <cuda_runtime.h>
#include <cuda_bf16.h>

// Problem constants
#define D_DIM   1024
#define D4      (D_DIM / 4)          // 256 float4 lanes
#define L_COMP  16384
#define L_FULL  32768
#define EPS_P   1e-4f

#define CHUNK_T 64                   // positions per chunk
#define NCHUNK  (L_COMP / CHUNK_T)   // 256 chunks

// Scratch (allocation-free rule: __device__ globals)
__device__ float  g_p[L_COMP];               // clipped p
__device__ float  g_A[NCHUNK];               // per-chunk decay product (scalar)
__device__ float4 g_Z[NCHUNK * D4];          // chunk-local scan endpoints
__device__ float4 g_carry[NCHUNK * D4];      // carry entering each chunk
__device__ int    g_pos[L_COMP + 1];         // boundary positions; g_pos[L_COMP] = L_FULL

// ---------------------------------------------------------------------------
// prep: blocks 0..15 clip p; block 16 chunk products; block 17 scans b -> pos
// ---------------------------------------------------------------------------
__global__ void k_prep(const float* __restrict__ ps, const int* __restrict__ b) {
    int blk = blockIdx.x;
    int tid = threadIdx.x;
    if (blk < 16) {
        int i = blk * 1024 + tid;
        float p = ps[i];
        p = fminf(fmaxf(p, EPS_P), 1.0f - EPS_P);
        g_p[i] = p;
    } else if (blk == 16) {
        if (tid < NCHUNK) {
            int t0 = tid * CHUNK_T;
            float prod = 1.0f;
            #pragma unroll 8
            for (int t = 0; t < CHUNK_T; t++) {
                float p = ps[t0 + t];
                p = fminf(fmaxf(p, EPS_P), 1.0f - EPS_P);
                prod *= (1.0f - p);
            }
            g_A[tid] = prod;
        }
    } else {
        // boundary position scan: 1024 threads x 32 elements = 32768
        __shared__ int s[1024];
        int base = tid * 32;
        int cnt = 0;
        #pragma unroll 8
        for (int i = 0; i < 32; i++) cnt += b[base + i];
        s[tid] = cnt;
        __syncthreads();
        for (int off = 1; off < 1024; off <<= 1) {
            int v = s[tid];
            int u = (tid >= off) ? s[tid - off] : 0;
            __syncthreads();
            s[tid] = v + u;
            __syncthreads();
        }
        int run = s[tid] - cnt;  // exclusive prefix
        #pragma unroll 8
        for (int i = 0; i < 32; i++) {
            if (b[base + i]) g_pos[run++] = base + i;
        }
        if (tid == 1023) g_pos[s[1023]] = L_FULL;
    }
}

// ---------------------------------------------------------------------------
// pass1: chunk-local scans from zero -> Z endpoints.
// grid = NCHUNK blocks, 256 threads, each thread owns 4 channels (float4).
// ---------------------------------------------------------------------------
__global__ void __launch_bounds__(D4) k_pass1(const float4* __restrict__ x) {
    int c  = blockIdx.x;
    int d4 = threadIdx.x;
    int t0 = c * CHUNK_T;

    __shared__ float sp[CHUNK_T];
    if (d4 < CHUNK_T) sp[d4] = g_p[t0 + d4];
    __syncthreads();

    const float4* xp = x + (size_t)t0 * D4 + d4;
    float4 z = make_float4(0.f, 0.f, 0.f, 0.f);
    #pragma unroll 8
    for (int t = 0; t < CHUNK_T; t++) {
        float p = sp[t];
        float a = 1.0f - p;
        float4 xv = xp[(size_t)t * D4];      // LDG.128, coalesced 4KB/block-row
        z.x = fmaf(a, z.x, p * xv.x);
        z.y = fmaf(a, z.y, p * xv.y);
        z.z = fmaf(a, z.z, p * xv.z);
        z.w = fmaf(a, z.w, p * xv.w);
    }
    g_Z[c * D4 + d4] = z;
}

// ---------------------------------------------------------------------------
// pass2: cross-chunk recurrence; one block, 256 threads x 4 channels
// ---------------------------------------------------------------------------
__global__ void __launch_bounds__(D4) k_pass2() {
    int d4 = threadIdx.x;
    float4 carry = make_float4(0.f, 0.f, 0.f, 0.f);
    for (int c0 = 0; c0 < NCHUNK; c0 += 8) {
        float4 zb[8]; float ab[8];
        #pragma unroll
        for (int j = 0; j < 8; j++) {
            zb[j] = g_Z[(c0 + j) * D4 + d4];
            ab[j] = g_A[c0 + j];
        }
        #pragma unroll
        for (int j = 0; j < 8; j++) {
            g_carry[(c0 + j) * D4 + d4] = carry;
            float a = ab[j];
            carry.x = fmaf(a, carry.x, zb[j].x);
            carry.y = fmaf(a, carry.y, zb[j].y);
            carry.z = fmaf(a, carry.z, zb[j].z);
            carry.w = fmaf(a, carry.w, zb[j].w);
        }
    }
}

// ---------------------------------------------------------------------------
// pass3: re-scan with carry, fused scatter-replicate into out.
// grid = NCHUNK blocks, 256 threads x 4 channels. Streaming stores keep x in L2.
// ---------------------------------------------------------------------------
__global__ void __launch_bounds__(D4) k_pass3(const float4* __restrict__ x,
                                              float4* __restrict__ out) {
    int c  = blockIdx.x;
    int d4 = threadIdx.x;
    int t0 = c * CHUNK_T;

    __shared__ float sp[CHUNK_T];
    __shared__ int   spos[CHUNK_T + 1];
    if (d4 < CHUNK_T)     sp[d4]   = g_p[t0 + d4];
    if (d4 < CHUNK_T + 1) spos[d4] = g_pos[t0 + d4];
    __syncthreads();

    const float4* xp = x + (size_t)t0 * D4 + d4;
    float4 z = g_carry[c * D4 + d4];

    int seg_s = spos[0];
    #pragma unroll 4
    for (int t = 0; t < CHUNK_T; t++) {
        float p = sp[t];
        float a = 1.0f - p;
        float4 xv = xp[(size_t)t * D4];
        z.x = fmaf(a, z.x, p * xv.x);
        z.y = fmaf(a, z.y, p * xv.y);
        z.z = fmaf(a, z.z, p * xv.z);
        z.w = fmaf(a, z.w, p * xv.w);
        int seg_e = spos[t + 1];                 // smem, off the mem path
        for (int tf = seg_s; tf < seg_e; tf++) { // warp-uniform trip count
            // streaming store: out is write-once, keep L2 for x
            __stcs(out + (size_t)tf * D4 + d4, z);
        }
        seg_s = seg_e;
    }
}

// ---------------------------------------------------------------------------
extern "C" void kernel_launch(void* const* d_in, const int* in_sizes, int n_in,
                              void* d_out, int out_size) {
    const float* x  = (const float*)d_in[0];   // (1, 16384, 1024) f32
    const float* ps = (const float*)d_in[1];   // (16384,) f32
    const int*   b  = (const int*)d_in[2];     // (1, 32768) i32
    float4* out = (float4*)d_out;              // (1, 32768, 1024) f32

    k_prep<<<18, 1024>>>(ps, b);
    k_pass1<<<NCHUNK, D4>>>((const float4*)x);
    k_pass2<<<1, D4>>>();
    k_pass3<<<NCHUNK, D4>>>((const float4*)x, out);
}

// round 8
// speedup vs baseline: 1.6139x; 1.2860x over previous
#include <cuda_runtime.h>
#include <cuda_bf16.h>

// Problem constants
#define D_DIM   1024
#define D4      (D_DIM / 4)          // 256 float4 lanes
#define L_COMP  16384
#define L_FULL  32768
#define EPS_P   1e-4f

#define CHUNK_T 16                   // positions per chunk
#define NCHUNK  (L_COMP / CHUNK_T)   // 1024 chunks

// Scratch (allocation-free rule: __device__ globals)
__device__ float  g_A[NCHUNK];               // per-chunk decay product (scalar)
__device__ float4 g_Z[NCHUNK * D4];          // chunk-local scan endpoints
__device__ int    g_flag[NCHUNK];            // 0 = not ready, 1 = Z/A published
__device__ int    g_pos[L_COMP + 1];         // boundary positions; [L_COMP] = L_FULL

__device__ __forceinline__ int ld_acquire(const int* p) {
    int v;
    asm volatile("ld.acquire.gpu.global.b32 %0, [%1];" : "=r"(v) : "l"(p));
    return v;
}
__device__ __forceinline__ void st_release(int* p, int v) {
    asm volatile("st.release.gpu.global.b32 [%0], %1;" :: "l"(p), "r"(v));
}

// ---------------------------------------------------------------------------
// prep: block 0 scans b -> pos; block 1 zeroes flags (must happen EVERY launch
// so graph replays are deterministic)
// ---------------------------------------------------------------------------
__global__ void k_prep(const int* __restrict__ b) {
    int tid = threadIdx.x;
    if (blockIdx.x == 1) {
        g_flag[tid] = 0;   // 1024 threads == NCHUNK
        return;
    }
    // boundary position scan: 1024 threads x 32 elements = 32768
    __shared__ int s[1024];
    int base = tid * 32;
    int cnt = 0;
    #pragma unroll 8
    for (int i = 0; i < 32; i++) cnt += b[base + i];
    s[tid] = cnt;
    __syncthreads();
    for (int off = 1; off < 1024; off <<= 1) {
        int v = s[tid];
        int u = (tid >= off) ? s[tid - off] : 0;
        __syncthreads();
        s[tid] = v + u;
        __syncthreads();
    }
    int run = s[tid] - cnt;  // exclusive prefix
    #pragma unroll 8
    for (int i = 0; i < 32; i++) {
        if (b[base + i]) g_pos[run++] = base + i;
    }
    if (tid == 1023) g_pos[s[1023]] = L_FULL;
}

// ---------------------------------------------------------------------------
// fused single-pass scan with decoupled lookback + scatter-replicate epilogue
// grid = NCHUNK (1024) blocks, 256 threads, thread owns 4 channels (float4)
// ---------------------------------------------------------------------------
__global__ void __launch_bounds__(D4) k_fused(const float4* __restrict__ x,
                                              const float* __restrict__ ps,
                                              float4* __restrict__ out) {
    int c  = blockIdx.x;
    int d4 = threadIdx.x;
    int t0 = c * CHUNK_T;

    __shared__ float sp[CHUNK_T];
    __shared__ int   spos[CHUNK_T + 1];
    __shared__ float s_a;

    if (d4 < CHUNK_T) {
        float p = ps[t0 + d4];
        sp[d4] = fminf(fmaxf(p, EPS_P), 1.0f - EPS_P);
    }
    if (d4 < CHUNK_T + 1) spos[d4] = g_pos[t0 + d4];
    __syncthreads();

    // ---- phase A: chunk-local scan (loads are the only DRAM read of x) ----
    const float4* xp = x + (size_t)t0 * D4 + d4;
    float4 z = make_float4(0.f, 0.f, 0.f, 0.f);
    #pragma unroll
    for (int t = 0; t < CHUNK_T; t++) {
        float p = sp[t];
        float a = 1.0f - p;
        float4 xv = xp[(size_t)t * D4];
        z.x = fmaf(a, z.x, p * xv.x);
        z.y = fmaf(a, z.y, p * xv.y);
        z.z = fmaf(a, z.z, p * xv.z);
        z.w = fmaf(a, z.w, p * xv.w);
    }
    g_Z[(size_t)c * D4 + d4] = z;
    if (d4 == 0) {
        float prod = 1.0f;
        #pragma unroll
        for (int t = 0; t < CHUNK_T; t++) prod *= (1.0f - sp[t]);
        g_A[c] = prod;
    }
    __syncthreads();                 // all Z/A writes issued
    if (d4 == 0) {
        __threadfence();             // make them visible device-wide
        st_release(&g_flag[c], 1);
    }

    // ---- lookback: accumulate carry from predecessors ----
    // amul = product of predecessor A's; p~U(0,1) makes A_chunk ~ e^-16, so
    // amul underflows past any significance within ~3-5 steps -> early exit.
    float4 carry = make_float4(0.f, 0.f, 0.f, 0.f);
    if (c > 0) {
        float amul = 1.0f;
        for (int j = c - 1; j >= 0; j--) {
            if (d4 == 0) {
                if (ld_acquire(&g_flag[j]) == 0) {
                    while (ld_acquire(&g_flag[j]) == 0) __nanosleep(40);
                }
                s_a = g_A[j];
            }
            __syncthreads();
            float aj = s_a;
            float4 zj = g_Z[(size_t)j * D4 + d4];
            carry.x = fmaf(amul, zj.x, carry.x);
            carry.y = fmaf(amul, zj.y, carry.y);
            carry.z = fmaf(amul, zj.z, carry.z);
            carry.w = fmaf(amul, zj.w, carry.w);
            amul *= aj;              // uniform across the block
            __syncthreads();         // protect s_a before next iteration
            if (amul < 1e-35f) break;
        }
    }

    // ---- phase B: re-scan from carry, scatter-replicate to out ----
    // x re-read hits L1/L2 (64 MiB of x fits entirely in the 126 MB L2).
    float4 zz = carry;
    int seg_s = spos[0];
    #pragma unroll
    for (int t = 0; t < CHUNK_T; t++) {
        float p = sp[t];
        float a = 1.0f - p;
        float4 xv = xp[(size_t)t * D4];
        zz.x = fmaf(a, zz.x, p * xv.x);
        zz.y = fmaf(a, zz.y, p * xv.y);
        zz.z = fmaf(a, zz.z, p * xv.z);
        zz.w = fmaf(a, zz.w, p * xv.w);
        int seg_e = spos[t + 1];                 // warp-uniform
        for (int tf = seg_s; tf < seg_e; tf++) { // warp-uniform trip count
            __stcs(out + (size_t)tf * D4 + d4, zz);  // write-once: evict-first
        }
        seg_s = seg_e;
    }
}

// ---------------------------------------------------------------------------
extern "C" void kernel_launch(void* const* d_in, const int* in_sizes, int n_in,
                              void* d_out, int out_size) {
    const float* x  = (const float*)d_in[0];   // (1, 16384, 1024) f32
    const float* ps = (const float*)d_in[1];   // (16384,) f32
    const int*   b  = (const int*)d_in[2];     // (1, 32768) i32
    float4* out = (float4*)d_out;              // (1, 32768, 1024) f32

    k_prep<<<2, 1024>>>(b);
    k_fused<<<NCHUNK, D4>>>((const float4*)x, ps, out);
}

// round 9
// speedup vs baseline: 2.7131x; 1.6811x over previous
#include <cuda_runtime.h>
#include <cuda_bf16.h>

// Problem constants
#define D_DIM   1024
#define D4      (D_DIM / 4)          // 256 float4 lanes
#define L_COMP  16384
#define L_FULL  32768
#define EPS_P   1e-4f

#define CHUNK_T 16                   // positions per chunk
#define NCHUNK  (L_COMP / CHUNK_T)   // 1024 chunks

// Scratch (allocation-free rule: __device__ globals)
__device__ float  g_A[NCHUNK];               // per-chunk decay product (scalar)
__device__ float4 g_Z[NCHUNK * D4];          // chunk-local scan endpoints
__device__ int    g_flag[NCHUNK];            // 0 = not ready, 1 = Z/A published
__device__ int    g_pos[L_COMP + 1];         // boundary positions; [L_COMP] = L_FULL

__device__ __forceinline__ int ld_acquire(const int* p) {
    int v;
    asm volatile("ld.acquire.gpu.global.b32 %0, [%1];" : "=r"(v) : "l"(p));
    return v;
}
__device__ __forceinline__ void st_release(int* p, int v) {
    asm volatile("st.release.gpu.global.b32 [%0], %1;" :: "l"(p), "r"(v));
}

// ---------------------------------------------------------------------------
// prep: block 0 scans b -> pos via warp ballots (coalesced); block 1 zeroes
// flags (must happen EVERY launch so graph replays are deterministic)
// ---------------------------------------------------------------------------
__global__ void k_prep(const int* __restrict__ b) {
    int tid = threadIdx.x;
    if (blockIdx.x == 1) {
        g_flag[tid] = 0;   // 1024 threads == NCHUNK
        return;
    }
    int w    = tid >> 5;
    int lane = tid & 31;
    int base = w * 1024;                 // warp-contiguous segment
    __shared__ int woff[32];

    // pass 1: per-warp one-count, coalesced loads (lane-adjacent addresses)
    int cnt = 0;
    #pragma unroll 8
    for (int i = 0; i < 32; i++) {
        int v = b[base + i * 32 + lane];
        unsigned m = __ballot_sync(0xffffffffu, v != 0);
        cnt += __popc(m);                // warp-uniform
    }
    if (lane == 0) woff[w] = cnt;
    __syncthreads();

    // warp 0: exclusive prefix over the 32 warp counts
    if (w == 0) {
        int orig = woff[lane];
        int incl = orig;
        #pragma unroll
        for (int off = 1; off < 32; off <<= 1) {
            int u = __shfl_up_sync(0xffffffffu, incl, off);
            if (lane >= off) incl += u;
        }
        woff[lane] = incl - orig;        // exclusive
    }
    __syncthreads();

    // pass 2: scatter positions (b re-read hits L1)
    int run = woff[w];
    #pragma unroll 8
    for (int i = 0; i < 32; i++) {
        int idx = base + i * 32 + lane;
        int v = b[idx];
        unsigned m = __ballot_sync(0xffffffffu, v != 0);
        if (v) g_pos[run + __popc(m & ((1u << lane) - 1u))] = idx;
        run += __popc(m);
    }
    if (tid == 0) g_pos[L_COMP] = L_FULL;
}

// ---------------------------------------------------------------------------
// fused single-pass scan with decoupled lookback + scatter-replicate epilogue
// grid = NCHUNK (1024) blocks, 256 threads, thread owns 4 channels (float4).
// minBlocksPerMultiprocessor=4 caps regs at 64 -> 32 warps/SM (occ 50%).
// ---------------------------------------------------------------------------
__global__ void __launch_bounds__(D4, 4) k_fused(const float4* __restrict__ x,
                                                 const float* __restrict__ ps,
                                                 float4* __restrict__ out) {
    int c  = blockIdx.x;
    int d4 = threadIdx.x;
    int t0 = c * CHUNK_T;

    __shared__ float sp[CHUNK_T];
    __shared__ int   spos[CHUNK_T + 1];
    __shared__ float s_a;

    if (d4 < CHUNK_T) {
        float p = ps[t0 + d4];
        sp[d4] = fminf(fmaxf(p, EPS_P), 1.0f - EPS_P);
    }
    if (d4 < CHUNK_T + 1) spos[d4] = g_pos[t0 + d4];
    __syncthreads();

    // ---- phase A: chunk-local scan (the only DRAM read of x) ----
    const float4* xp = x + (size_t)t0 * D4 + d4;
    float4 z = make_float4(0.f, 0.f, 0.f, 0.f);
    #pragma unroll
    for (int t = 0; t < CHUNK_T; t++) {
        float p = sp[t];
        float a = 1.0f - p;
        float4 xv = xp[(size_t)t * D4];
        z.x = fmaf(a, z.x, p * xv.x);
        z.y = fmaf(a, z.y, p * xv.y);
        z.z = fmaf(a, z.z, p * xv.z);
        z.w = fmaf(a, z.w, p * xv.w);
    }
    g_Z[(size_t)c * D4 + d4] = z;
    if (d4 == 0) {
        float prod = 1.0f;
        #pragma unroll
        for (int t = 0; t < CHUNK_T; t++) prod *= (1.0f - sp[t]);
        g_A[c] = prod;
    }
    __syncthreads();                 // all Z/A writes issued
    if (d4 == 0) {
        __threadfence();             // make them visible device-wide
        st_release(&g_flag[c], 1);
    }

    // ---- lookback: accumulate carry from predecessors ----
    // p~U(0,1) => A_chunk ~ e^-16; amul underflows past any significance
    // within ~5 predecessors -> early exit keeps lookback O(1).
    float4 carry = make_float4(0.f, 0.f, 0.f, 0.f);
    if (c > 0) {
        float amul = 1.0f;
        for (int j = c - 1; j >= 0; j--) {
            if (d4 == 0) {
                if (ld_acquire(&g_flag[j]) == 0) {
                    while (ld_acquire(&g_flag[j]) == 0) __nanosleep(40);
                }
                s_a = g_A[j];
            }
            __syncthreads();
            float aj = s_a;
            float4 zj = g_Z[(size_t)j * D4 + d4];
            carry.x = fmaf(amul, zj.x, carry.x);
            carry.y = fmaf(amul, zj.y, carry.y);
            carry.z = fmaf(amul, zj.z, carry.z);
            carry.w = fmaf(amul, zj.w, carry.w);
            amul *= aj;              // uniform across the block
            __syncthreads();         // protect s_a before next iteration
            if (amul < 1e-35f) break;
        }
    }

    // ---- phase B: re-scan from carry, scatter-replicate to out ----
    // x re-read hits L1 (64 KiB slice/CTA, just touched in phase A).
    float4 zz = carry;
    int seg_s = spos[0];
    #pragma unroll
    for (int t = 0; t < CHUNK_T; t++) {
        float p = sp[t];
        float a = 1.0f - p;
        float4 xv = xp[(size_t)t * D4];
        zz.x = fmaf(a, zz.x, p * xv.x);
        zz.y = fmaf(a, zz.y, p * xv.y);
        zz.z = fmaf(a, zz.z, p * xv.z);
        zz.w = fmaf(a, zz.w, p * xv.w);
        int seg_e = spos[t + 1];                 // warp-uniform
        for (int tf = seg_s; tf < seg_e; tf++) { // warp-uniform trip count
            __stcs(out + (size_t)tf * D4 + d4, zz);  // write-once: evict-first
        }
        seg_s = seg_e;
    }
}

// ---------------------------------------------------------------------------
extern "C" void kernel_launch(void* const* d_in, const int* in_sizes, int n_in,
                              void* d_out, int out_size) {
    const float* x  = (const float*)d_in[0];   // (1, 16384, 1024) f32
    const float* ps = (const float*)d_in[1];   // (16384,) f32
    const int*   b  = (const int*)d_in[2];     // (1, 32768) i32
    float4* out = (float4*)d_out;              // (1, 32768, 1024) f32

    k_prep<<<2, 1024>>>(b);
    k_fused<<<NCHUNK, D4>>>((const float4*)x, ps, out);
}